// round 16
// baseline (speedup 1.0000x reference)
#include <cuda_runtime.h>
#include <cuda_bf16.h>
#include <stdint.h>

// WeightsDropout: per row of [8192,1,4096] f32, zero the 2048 smallest
// (stable-argsort tie-break by index), softmax over survivors.
//
// Champion chassis (R15, 55.8us): 256 thr/CTA, 6 CTAs/SM, loads before
// init barrier, warp-0 scan, float-bound gather, warp-0 threshold key +
// tie flag, tie-free pass 3, thread-local final reduce.
// This round: window narrowed 4x to [0.4375, 0.5625) (6.25% of uniform
// elements; boundary is ~0.5 +- 8 sigma inside) -> 4x fewer pass-1
// shared atomics. 256 bins of width 1/4096 (lambda=1). Exact full-range
// fallback unchanged.

namespace {

constexpr int N        = 4096;
constexpr int KDROP    = 2048;
constexpr int THREADS  = 256;
constexpr int VEC      = N / 4 / THREADS;   // 4 float4 per thread
constexpr int NWARP    = THREADS / 32;      // 8
constexpr int NB       = 256;
constexpr int CAND_CAP = 256;

constexpr float WSC  = 4096.0f;             // 256 bins over [0.4375, 0.5625)
constexpr float WOFF = -1792.0f;            // -0.4375 * 4096

__global__ __launch_bounds__(THREADS, 6)
void wdrop_kernel(const float* __restrict__ in, float* __restrict__ out)
{
    __shared__ unsigned hist[NB];
    __shared__ unsigned long long cand[CAND_CAP];
    __shared__ unsigned cand_n;
    __shared__ float    s_redf[NWARP];
    __shared__ unsigned s_redu[NWARP];
    __shared__ unsigned s_bin, s_rank, s_found, s_tie;
    __shared__ unsigned long long s_thr;

    const int t    = threadIdx.x;
    const int lane = t & 31;
    const int warp = t >> 5;

    const long long row = blockIdx.x;
    const float4* __restrict__ in4  = reinterpret_cast<const float4*>(in  + row * (long long)N);
    float4*       __restrict__ out4 = reinterpret_cast<float4*>      (out + row * (long long)N);

    // ---- issue row loads FIRST: LDG latency overlaps the init barrier ----
    float4 xs[VEC];
#pragma unroll
    for (int j = 0; j < VEC; j++) xs[j] = in4[t + THREADS * j];

    hist[t] = 0u;                          // NB == THREADS
    if (t == 0) { cand_n = 0u; s_found = 0u; s_tie = 0u; }
    __syncthreads();                       // B1: init (loads in flight)

    // ---- pass 1: below-count + narrow-window histogram ----
    unsigned below = 0;
#pragma unroll
    for (int j = 0; j < VEC; j++) {
        float vv[4] = {xs[j].x, xs[j].y, xs[j].z, xs[j].w};
#pragma unroll
        for (int c = 0; c < 4; c++) {
            int b = __float2int_rd(fmaf(vv[c], WSC, WOFF));
            below += (b < 0) ? 1u : 0u;
            if ((unsigned)b < (unsigned)NB) atomicAdd(&hist[b], 1u);
        }
    }
#pragma unroll
    for (int o = 16; o; o >>= 1)
        below += __shfl_xor_sync(0xffffffffu, below, o);
    if (lane == 0) s_redu[warp] = below;
    __syncthreads();                       // B2: hist + below partials ready

    // ---- warp 0: combine below; scan histogram for rank-KDROP bin ----
    if (warp == 0) {
        unsigned b = (lane < NWARP) ? s_redu[lane] : 0u;
#pragma unroll
        for (int o = 16; o; o >>= 1)
            b += __shfl_xor_sync(0xffffffffu, b, o);

        unsigned c8[8]; unsigned sum = 0;
#pragma unroll
        for (int i = 0; i < 8; i++) { c8[i] = hist[lane * 8 + i]; sum += c8[i]; }
        unsigned inc = sum;
#pragma unroll
        for (int o = 1; o < 32; o <<= 1) {
            unsigned nn = __shfl_up_sync(0xffffffffu, inc, o);
            if (lane >= o) inc += nn;
        }
        unsigned c = b + inc - sum;
#pragma unroll
        for (int i = 0; i < 8; i++) {
            unsigned cc = c8[i];
            if (c <= (unsigned)KDROP && (unsigned)KDROP < c + cc) {
                s_bin = (unsigned)(lane * 8 + i);
                s_rank = (unsigned)KDROP - c;
                s_found = 1u;
            }
            c += cc;
        }
    }
    __syncthreads();                       // B3: bstar/rstar ready

    // ---- fallback: boundary outside window (ultra-rare, still exact) ----
    bool fb = !s_found;
    if (fb) {
        hist[t] = 0u;
        __syncthreads();
#pragma unroll
        for (int j = 0; j < VEC; j++) {
            float vv[4] = {xs[j].x, xs[j].y, xs[j].z, xs[j].w};
#pragma unroll
            for (int c = 0; c < 4; c++) {
                int b = __float2int_rd(vv[c] * 256.0f);
                b = max(min(b, NB - 1), 0);
                atomicAdd(&hist[b], 1u);
            }
        }
        __syncthreads();
        if (warp == 0) {
            unsigned c8[8]; unsigned sum = 0;
#pragma unroll
            for (int i = 0; i < 8; i++) { c8[i] = hist[lane * 8 + i]; sum += c8[i]; }
            unsigned inc = sum;
#pragma unroll
            for (int o = 1; o < 32; o <<= 1) {
                unsigned nn = __shfl_up_sync(0xffffffffu, inc, o);
                if (lane >= o) inc += nn;
            }
            unsigned c = inc - sum;
#pragma unroll
            for (int i = 0; i < 8; i++) {
                unsigned cc = c8[i];
                if (c <= (unsigned)KDROP && (unsigned)KDROP < c + cc) {
                    s_bin = (unsigned)(lane * 8 + i);
                    s_rank = (unsigned)KDROP - c;
                }
                c += cc;
            }
        }
        __syncthreads();
    }

    const unsigned bstar = s_bin;
    const unsigned rstar = s_rank;

    // exact float bounds of the boundary bin (powers-of-two scaling)
    float blo, bhi;
    if (!fb) {
        blo = (float)(bstar + 1792u) * (1.0f / 4096.0f);
        bhi = (float)(bstar + 1793u) * (1.0f / 4096.0f);
    } else {
        blo = (bstar == 0u)      ? -3.4e38f : (float)bstar        * (1.0f / 256.0f);
        bhi = (bstar == NB - 1u) ?  3.4e38f : (float)(bstar + 1u) * (1.0f / 256.0f);
    }

    // ---- gather boundary-bin candidates (two FSETPs per element) ----
#pragma unroll
    for (int j = 0; j < VEC; j++) {
        float vv[4] = {xs[j].x, xs[j].y, xs[j].z, xs[j].w};
#pragma unroll
        for (int c = 0; c < 4; c++) {
            float val = vv[c];
            if (val >= blo && val < bhi) {
                unsigned p = atomicAdd(&cand_n, 1u);
                if (p < (unsigned)CAND_CAP) {
                    unsigned idx = (unsigned)(4 * (t + THREADS * j) + c);
                    cand[p] = ((unsigned long long)__float_as_uint(val) << 12)
                            | (unsigned long long)idx;
                }
            }
        }
    }
    __syncthreads();                       // B4: cand ready

    // ---- warp 0: threshold key + tie detection ----
    if (warp == 0) {
        unsigned c = min(cand_n, (unsigned)CAND_CAP);
        unsigned long long thr_loc = 0ull;
        for (unsigned bq = 0; bq < c; bq += 32) {
            unsigned q = bq + lane;
            bool hit = false;
            unsigned long long k = 0ull;
            if (q < c) {
                k = cand[q];
                unsigned rk = 0;
                for (unsigned i = 0; i < c; i++) rk += (cand[i] < k) ? 1u : 0u;
                hit = (rk == rstar);
            }
            unsigned msk = __ballot_sync(0xffffffffu, hit);
            if (msk) thr_loc = __shfl_sync(0xffffffffu, k, __ffs(msk) - 1);
        }
        if (lane == 0) s_thr = thr_loc;
        unsigned thr_bits = (unsigned)(thr_loc >> 12);
        bool tiel = false;
        for (unsigned q = lane; q < c; q += 32) {
            unsigned long long k = cand[q];
            if (k < thr_loc && (unsigned)(k >> 12) == thr_bits) tiel = true;
        }
        if (__ballot_sync(0xffffffffu, tiel) && lane == 0) s_tie = 1u;
    }
    __syncthreads();                       // B5: thr/tie ready

    const unsigned long long thr = s_thr;
    const float    thr_val = __uint_as_float((unsigned)(thr >> 12));
    const unsigned tie     = s_tie;

    // ---- pass 3: keep + exp + sum ----
    float lsum = 0.0f;
    if (!tie) {
#pragma unroll
        for (int j = 0; j < VEC; j++) {
            float vv[4] = {xs[j].x, xs[j].y, xs[j].z, xs[j].w};
            float ee[4];
#pragma unroll
            for (int c = 0; c < 4; c++) {
                float val = vv[c];
                float e = (val >= thr_val) ? __expf(val) : 0.0f;
                ee[c] = e;
                lsum += e;
            }
            xs[j].x = ee[0]; xs[j].y = ee[1]; xs[j].z = ee[2]; xs[j].w = ee[3];
        }
    } else {
        const unsigned thr_idx = (unsigned)(thr & 0xFFFull);
#pragma unroll
        for (int j = 0; j < VEC; j++) {
            float vv[4] = {xs[j].x, xs[j].y, xs[j].z, xs[j].w};
            float ee[4];
#pragma unroll
            for (int c = 0; c < 4; c++) {
                float val = vv[c];
                unsigned idx = (unsigned)(4 * (t + THREADS * j) + c);
                bool keep = (val > thr_val) || (val == thr_val && idx >= thr_idx);
                float e = keep ? __expf(val) : 0.0f;
                ee[c] = e;
                lsum += e;
            }
            xs[j].x = ee[0]; xs[j].y = ee[1]; xs[j].z = ee[2]; xs[j].w = ee[3];
        }
    }
#pragma unroll
    for (int o = 16; o; o >>= 1) lsum += __shfl_xor_sync(0xffffffffu, lsum, o);
    if (lane == 0) s_redf[warp] = lsum;
    __syncthreads();                       // B6: partials ready

    // ---- every thread: final sum + inv (broadcast smem reads) ----
    float s = s_redf[0];
#pragma unroll
    for (int i = 1; i < NWARP; i++) s += s_redf[i];
    const float inv = 1.0f / s;

    // ---- scaled store from registers ----
#pragma unroll
    for (int j = 0; j < VEC; j++) {
        float4 o4 = {xs[j].x * inv, xs[j].y * inv, xs[j].z * inv, xs[j].w * inv};
        out4[t + THREADS * j] = o4;
    }
}

} // anonymous namespace

extern "C" void kernel_launch(void* const* d_in, const int* in_sizes, int n_in,
                              void* d_out, int out_size)
{
    (void)n_in; (void)in_sizes;
    const float* w = (const float*)d_in[0];
    float* outp = (float*)d_out;
    int rows = out_size / N;            // 8192
    wdrop_kernel<<<rows, THREADS>>>(w, outp);
}

// round 17
// speedup vs baseline: 1.1185x; 1.1185x over previous
#include <cuda_runtime.h>
#include <cuda_bf16.h>
#include <stdint.h>

// WeightsDropout: per row of [8192,1,4096] f32, zero the 2048 smallest
// (stable-argsort tie-break by index), softmax over survivors.
//
// Champion chassis (R15, 55.8us): 256 thr/CTA, 6 CTAs/SM, loads before
// init barrier, 256-bin window hist over [0.375,0.625) + below-count,
// warp-0 scan, float-bound gather, warp-0 threshold key + tie flag,
// tie-free single-compare pass 3, thread-local final reduce.
// This round: __stcs streaming stores (output written once, never read)
// to keep the 128MB output from polluting L2. Everything else identical.

namespace {

constexpr int N        = 4096;
constexpr int KDROP    = 2048;
constexpr int THREADS  = 256;
constexpr int VEC      = N / 4 / THREADS;   // 4 float4 per thread
constexpr int NWARP    = THREADS / 32;      // 8
constexpr int NB       = 256;
constexpr int CAND_CAP = 256;

constexpr float WSC  = 1024.0f;             // 256 bins over [0.375, 0.625)
constexpr float WOFF = -384.0f;             // -0.375 * 1024

__global__ __launch_bounds__(THREADS, 6)
void wdrop_kernel(const float* __restrict__ in, float* __restrict__ out)
{
    __shared__ unsigned hist[NB];
    __shared__ unsigned long long cand[CAND_CAP];
    __shared__ unsigned cand_n;
    __shared__ float    s_redf[NWARP];
    __shared__ unsigned s_redu[NWARP];
    __shared__ unsigned s_bin, s_rank, s_found, s_tie;
    __shared__ unsigned long long s_thr;

    const int t    = threadIdx.x;
    const int lane = t & 31;
    const int warp = t >> 5;

    const long long row = blockIdx.x;
    const float4* __restrict__ in4  = reinterpret_cast<const float4*>(in  + row * (long long)N);
    float4*       __restrict__ out4 = reinterpret_cast<float4*>      (out + row * (long long)N);

    // ---- issue row loads FIRST: LDG latency overlaps the init barrier ----
    float4 xs[VEC];
#pragma unroll
    for (int j = 0; j < VEC; j++) xs[j] = in4[t + THREADS * j];

    hist[t] = 0u;                          // NB == THREADS
    if (t == 0) { cand_n = 0u; s_found = 0u; s_tie = 0u; }
    __syncthreads();                       // B1: init (loads in flight)

    // ---- pass 1: below-count + window histogram ----
    unsigned below = 0;
#pragma unroll
    for (int j = 0; j < VEC; j++) {
        float vv[4] = {xs[j].x, xs[j].y, xs[j].z, xs[j].w};
#pragma unroll
        for (int c = 0; c < 4; c++) {
            int b = __float2int_rd(fmaf(vv[c], WSC, WOFF));
            below += (b < 0) ? 1u : 0u;
            if ((unsigned)b < (unsigned)NB) atomicAdd(&hist[b], 1u);
        }
    }
#pragma unroll
    for (int o = 16; o; o >>= 1)
        below += __shfl_xor_sync(0xffffffffu, below, o);
    if (lane == 0) s_redu[warp] = below;
    __syncthreads();                       // B2: hist + below partials ready

    // ---- warp 0: combine below; scan histogram for rank-KDROP bin ----
    if (warp == 0) {
        unsigned b = (lane < NWARP) ? s_redu[lane] : 0u;
#pragma unroll
        for (int o = 16; o; o >>= 1)
            b += __shfl_xor_sync(0xffffffffu, b, o);

        unsigned c8[8]; unsigned sum = 0;
#pragma unroll
        for (int i = 0; i < 8; i++) { c8[i] = hist[lane * 8 + i]; sum += c8[i]; }
        unsigned inc = sum;
#pragma unroll
        for (int o = 1; o < 32; o <<= 1) {
            unsigned nn = __shfl_up_sync(0xffffffffu, inc, o);
            if (lane >= o) inc += nn;
        }
        unsigned c = b + inc - sum;
#pragma unroll
        for (int i = 0; i < 8; i++) {
            unsigned cc = c8[i];
            if (c <= (unsigned)KDROP && (unsigned)KDROP < c + cc) {
                s_bin = (unsigned)(lane * 8 + i);
                s_rank = (unsigned)KDROP - c;
                s_found = 1u;
            }
            c += cc;
        }
    }
    __syncthreads();                       // B3: bstar/rstar ready

    // ---- fallback: boundary outside window (ultra-rare, still exact) ----
    bool fb = !s_found;
    if (fb) {
        hist[t] = 0u;
        __syncthreads();
#pragma unroll
        for (int j = 0; j < VEC; j++) {
            float vv[4] = {xs[j].x, xs[j].y, xs[j].z, xs[j].w};
#pragma unroll
            for (int c = 0; c < 4; c++) {
                int b = __float2int_rd(vv[c] * 256.0f);
                b = max(min(b, NB - 1), 0);
                atomicAdd(&hist[b], 1u);
            }
        }
        __syncthreads();
        if (warp == 0) {
            unsigned c8[8]; unsigned sum = 0;
#pragma unroll
            for (int i = 0; i < 8; i++) { c8[i] = hist[lane * 8 + i]; sum += c8[i]; }
            unsigned inc = sum;
#pragma unroll
            for (int o = 1; o < 32; o <<= 1) {
                unsigned nn = __shfl_up_sync(0xffffffffu, inc, o);
                if (lane >= o) inc += nn;
            }
            unsigned c = inc - sum;
#pragma unroll
            for (int i = 0; i < 8; i++) {
                unsigned cc = c8[i];
                if (c <= (unsigned)KDROP && (unsigned)KDROP < c + cc) {
                    s_bin = (unsigned)(lane * 8 + i);
                    s_rank = (unsigned)KDROP - c;
                }
                c += cc;
            }
        }
        __syncthreads();
    }

    const unsigned bstar = s_bin;
    const unsigned rstar = s_rank;

    // exact float bounds of the boundary bin (powers-of-two scaling)
    float blo, bhi;
    if (!fb) {
        blo = (float)(bstar + 384u) * (1.0f / 1024.0f);
        bhi = (float)(bstar + 385u) * (1.0f / 1024.0f);
    } else {
        blo = (bstar == 0u)      ? -3.4e38f : (float)bstar        * (1.0f / 256.0f);
        bhi = (bstar == NB - 1u) ?  3.4e38f : (float)(bstar + 1u) * (1.0f / 256.0f);
    }

    // ---- gather boundary-bin candidates (two FSETPs per element) ----
#pragma unroll
    for (int j = 0; j < VEC; j++) {
        float vv[4] = {xs[j].x, xs[j].y, xs[j].z, xs[j].w};
#pragma unroll
        for (int c = 0; c < 4; c++) {
            float val = vv[c];
            if (val >= blo && val < bhi) {
                unsigned p = atomicAdd(&cand_n, 1u);
                if (p < (unsigned)CAND_CAP) {
                    unsigned idx = (unsigned)(4 * (t + THREADS * j) + c);
                    cand[p] = ((unsigned long long)__float_as_uint(val) << 12)
                            | (unsigned long long)idx;
                }
            }
        }
    }
    __syncthreads();                       // B4: cand ready

    // ---- warp 0: threshold key + tie detection ----
    if (warp == 0) {
        unsigned c = min(cand_n, (unsigned)CAND_CAP);
        unsigned long long thr_loc = 0ull;
        for (unsigned bq = 0; bq < c; bq += 32) {
            unsigned q = bq + lane;
            bool hit = false;
            unsigned long long k = 0ull;
            if (q < c) {
                k = cand[q];
                unsigned rk = 0;
                for (unsigned i = 0; i < c; i++) rk += (cand[i] < k) ? 1u : 0u;
                hit = (rk == rstar);
            }
            unsigned msk = __ballot_sync(0xffffffffu, hit);
            if (msk) thr_loc = __shfl_sync(0xffffffffu, k, __ffs(msk) - 1);
        }
        if (lane == 0) s_thr = thr_loc;
        unsigned thr_bits = (unsigned)(thr_loc >> 12);
        bool tiel = false;
        for (unsigned q = lane; q < c; q += 32) {
            unsigned long long k = cand[q];
            if (k < thr_loc && (unsigned)(k >> 12) == thr_bits) tiel = true;
        }
        if (__ballot_sync(0xffffffffu, tiel) && lane == 0) s_tie = 1u;
    }
    __syncthreads();                       // B5: thr/tie ready

    const unsigned long long thr = s_thr;
    const float    thr_val = __uint_as_float((unsigned)(thr >> 12));
    const unsigned tie     = s_tie;

    // ---- pass 3: keep + exp + sum ----
    float lsum = 0.0f;
    if (!tie) {
#pragma unroll
        for (int j = 0; j < VEC; j++) {
            float vv[4] = {xs[j].x, xs[j].y, xs[j].z, xs[j].w};
            float ee[4];
#pragma unroll
            for (int c = 0; c < 4; c++) {
                float val = vv[c];
                float e = (val >= thr_val) ? __expf(val) : 0.0f;
                ee[c] = e;
                lsum += e;
            }
            xs[j].x = ee[0]; xs[j].y = ee[1]; xs[j].z = ee[2]; xs[j].w = ee[3];
        }
    } else {
        const unsigned thr_idx = (unsigned)(thr & 0xFFFull);
#pragma unroll
        for (int j = 0; j < VEC; j++) {
            float vv[4] = {xs[j].x, xs[j].y, xs[j].z, xs[j].w};
            float ee[4];
#pragma unroll
            for (int c = 0; c < 4; c++) {
                float val = vv[c];
                unsigned idx = (unsigned)(4 * (t + THREADS * j) + c);
                bool keep = (val > thr_val) || (val == thr_val && idx >= thr_idx);
                float e = keep ? __expf(val) : 0.0f;
                ee[c] = e;
                lsum += e;
            }
            xs[j].x = ee[0]; xs[j].y = ee[1]; xs[j].z = ee[2]; xs[j].w = ee[3];
        }
    }
#pragma unroll
    for (int o = 16; o; o >>= 1) lsum += __shfl_xor_sync(0xffffffffu, lsum, o);
    if (lane == 0) s_redf[warp] = lsum;
    __syncthreads();                       // B6: partials ready

    // ---- every thread: final sum + inv (broadcast smem reads) ----
    float s = s_redf[0];
#pragma unroll
    for (int i = 1; i < NWARP; i++) s += s_redf[i];
    const float inv = 1.0f / s;

    // ---- scaled streaming store (output never re-read; keep L2 clean) ----
#pragma unroll
    for (int j = 0; j < VEC; j++) {
        float4 o4 = {xs[j].x * inv, xs[j].y * inv, xs[j].z * inv, xs[j].w * inv};
        __stcs(out4 + t + THREADS * j, o4);
    }
}

} // anonymous namespace

extern "C" void kernel_launch(void* const* d_in, const int* in_sizes, int n_in,
                              void* d_out, int out_size)
{
    (void)n_in; (void)in_sizes;
    const float* w = (const float*)d_in[0];
    float* outp = (float*)d_out;
    int rows = out_size / N;            // 8192
    wdrop_kernel<<<rows, THREADS>>>(w, outp);
}